// round 11
// baseline (speedup 1.0000x reference)
#include <cuda_runtime.h>
#include <cuda_bf16.h>
#include <cuda_fp16.h>
#include <cstdint>

#define N_NODES 50000
#define N_EDGES 800000
#define DIM     128
#define NGRAPH  64

// ---------------- scratch (static device globals; no allocation) ----------------
__device__ __nv_bfloat16 g_Ahi[N_NODES * DIM];   // GEMM input (bf16)
__device__ int           g_q  [N_NODES * 32];    // GEMM output, int8 rows (32 x int32 per row)
__device__ float         g_rsc[N_NODES];         // per-row dequant scale for g_q
__device__ __nv_bfloat16 g_Whi[3 * DIM * DIM];   // W^T hi  [layer][n][k]
__device__ __nv_bfloat16 g_Wlo[3 * DIM * DIM];   // W^T lo  [layer][n][k]  (W error is node-correlated
                                                 //  -> does NOT pool-average; split required)
__device__ int   g_deg[N_NODES];
__device__ float g_dinv[N_NODES];
__device__ int   g_off[N_NODES + 1];
__device__ int   g_cur[N_NODES];                 // preloaded with offsets by k_scan
__device__ int   g_csrc[N_EDGES];
__device__ float g_cnrm[N_EDGES];
__device__ int   g_is64;
#define PCH 16
__device__ float g_pool[PCH * NGRAPH * DIM];

// ---------------- small helpers ----------------
__device__ __forceinline__ int ldidx(const void* __restrict__ p, long long i) {
    if (g_is64) return (int)((const long long*)p)[i];
    return ((const int*)p)[i];
}
__device__ __forceinline__ uint32_t smem_u32(const void* p) {
    uint32_t a;
    asm("{ .reg .u64 t; cvta.to.shared.u64 t, %1; cvt.u32.u64 %0, t; }" : "=r"(a) : "l"(p));
    return a;
}
__device__ __forceinline__ uint32_t packbf2(float a, float b) {
    __nv_bfloat162 t = __floats2bfloat162_rn(a, b);
    return *reinterpret_cast<uint32_t*>(&t);
}

// ---------------- init + dtype detection (fused) ----------------
__global__ void k_init(const int* __restrict__ probe) {
    int i = blockIdx.x * blockDim.x + threadIdx.x;
    if (i < N_NODES) g_deg[i] = 0;
    if (blockIdx.x == 0) {
        __shared__ int nz;
        if (threadIdx.x == 0) nz = 0;
        __syncthreads();
        if (threadIdx.x < 256 && probe[threadIdx.x * 2 + 1] != 0) atomicAdd(&nz, 1);
        __syncthreads();
        if (threadIdx.x == 0) g_is64 = (nz == 0) ? 1 : 0;
    }
}

// 2 edges per thread, vectorized dst loads
__global__ void k_degree(const void* __restrict__ ei) {
    int t = blockIdx.x * blockDim.x + threadIdx.x;
    if (t >= N_EDGES / 2) return;
    int d0, d1;
    if (g_is64) {
        longlong2 v = ((const longlong2*)((const long long*)ei + N_EDGES))[t];
        d0 = (int)v.x; d1 = (int)v.y;
    } else {
        int2 v = ((const int2*)((const int*)ei + N_EDGES))[t];
        d0 = v.x; d1 = v.y;
    }
    atomicAdd(&g_deg[d0], 1);
    atomicAdd(&g_deg[d1], 1);
}

// scan; dinv fused; preloads g_cur with the running offset (fill uses 1 atomic)
__global__ void k_scan() {
    __shared__ int part[1024];
    const int CH = (N_NODES + 1023) / 1024;
    int t = threadIdx.x;
    int b = t * CH;
    int e = b + CH; if (e > N_NODES) e = N_NODES;
    int s = 0;
    for (int i = b; i < e; i++) {
        int d = g_deg[i];
        g_dinv[i] = rsqrtf((float)(d + 1));
        s += d;
    }
    part[t] = s;
    __syncthreads();
    for (int d = 1; d < 1024; d <<= 1) {
        int v = (t >= d) ? part[t - d] : 0;
        __syncthreads();
        part[t] += v;
        __syncthreads();
    }
    int run = (t > 0) ? part[t - 1] : 0;
    for (int i = b; i < e; i++) {
        g_off[i] = run;
        g_cur[i] = run;
        run += g_deg[i];
    }
    if (t == 1023) g_off[N_NODES] = part[1023];
}

// fill CSR (2 edges/thread, single atomic per edge); low threads also split W (fused prepW)
__global__ void k_fill(const void* __restrict__ ei, const float* __restrict__ W0,
                       const float* __restrict__ W1, const float* __restrict__ W2) {
    int t = blockIdx.x * blockDim.x + threadIdx.x;
    if (t < 3 * DIM * DIM) {
        int L = t >> 14;
        int idx = t & (DIM * DIM - 1);
        const float* W = (L == 0) ? W0 : (L == 1) ? W1 : W2;
        int k = idx >> 7, n = idx & 127;
        float v = W[idx];
        __nv_bfloat16 hi = __float2bfloat16_rn(v);
        float lo = v - __bfloat162float(hi);
        g_Whi[L * DIM * DIM + n * DIM + k] = hi;
        g_Wlo[L * DIM * DIM + n * DIM + k] = __float2bfloat16_rn(lo);
    }
    if (t >= N_EDGES / 2) return;
    int s0, s1, d0, d1;
    if (g_is64) {
        longlong2 sv = ((const longlong2*)ei)[t];
        longlong2 dv = ((const longlong2*)((const long long*)ei + N_EDGES))[t];
        s0 = (int)sv.x; s1 = (int)sv.y; d0 = (int)dv.x; d1 = (int)dv.y;
    } else {
        int2 sv = ((const int2*)ei)[t];
        int2 dv = ((const int2*)((const int*)ei + N_EDGES))[t];
        s0 = sv.x; s1 = sv.y; d0 = dv.x; d1 = dv.y;
    }
    float fs0 = g_dinv[s0], fd0 = g_dinv[d0];
    float fs1 = g_dinv[s1], fd1 = g_dinv[d1];
    int p0 = atomicAdd(&g_cur[d0], 1);
    int p1 = atomicAdd(&g_cur[d1], 1);
    g_csrc[p0] = s0; g_cnrm[p0] = fs0 * fd0;
    g_csrc[p1] = s1; g_cnrm[p1] = fs1 * fd1;
}

// ---------------- mma.sync GEMM: hw[m][n] = sum_k A[m][k] * W[k][n] -> int8 rows --------
// A bf16, W bf16 split (2 products), fp32 accum; epilogue = per-row symmetric int8 quant.
#define SAS 272                 // smem row stride in BYTES (136 bf16)
#define SM_AH 0
#define SM_WH (64 * SAS)
#define SM_WL (192 * SAS)
#define SM_TOT (320 * SAS)      // 87,040 B

__device__ __forceinline__ void ldsm4(uint32_t addr, uint32_t* r) {
    asm volatile("ldmatrix.sync.aligned.m8n8.x4.shared.b16 {%0,%1,%2,%3}, [%4];"
                 : "=r"(r[0]), "=r"(r[1]), "=r"(r[2]), "=r"(r[3]) : "r"(addr));
}
__device__ __forceinline__ void mma16816(float* d, const uint32_t* a, uint32_t b0, uint32_t b1) {
    asm volatile(
        "mma.sync.aligned.m16n8k16.row.col.f32.bf16.bf16.f32 "
        "{%0,%1,%2,%3}, {%4,%5,%6,%7}, {%8,%9}, {%0,%1,%2,%3};"
        : "+f"(d[0]), "+f"(d[1]), "+f"(d[2]), "+f"(d[3])
        : "r"(a[0]), "r"(a[1]), "r"(a[2]), "r"(a[3]), "r"(b0), "r"(b1));
}

__global__ void __launch_bounds__(128) k_gemm_mma(int layer, const float* __restrict__ xsrc) {
    extern __shared__ char smem[];
    uint32_t sb = smem_u32(smem);
    int tid = threadIdx.x, wid = tid >> 5, lane = tid & 31;
    int m0 = blockIdx.x * 64;
    int valid = N_NODES - m0; if (valid > 64) valid = 64;

    // stage A (64 x 128 bf16)
    if (xsrc) {
        #pragma unroll
        for (int i = tid; i < 1024; i += 128) {
            int r = i >> 4, c = i & 15;
            uint4 vh = make_uint4(0, 0, 0, 0);
            if (r < valid) {
                const float4* xr = (const float4*)(xsrc + (long long)(m0 + r) * DIM) + c * 2;
                float4 f0 = xr[0], f1 = xr[1];
                vh.x = packbf2(f0.x, f0.y);
                vh.y = packbf2(f0.z, f0.w);
                vh.z = packbf2(f1.x, f1.y);
                vh.w = packbf2(f1.z, f1.w);
            }
            *(uint4*)(smem + SM_AH + r * SAS + c * 16) = vh;
        }
    } else {
        const uint4* gh = (const uint4*)(g_Ahi + (long long)m0 * DIM);
        #pragma unroll
        for (int i = tid; i < 1024; i += 128) {
            int r = i >> 4, c = i & 15;
            uint4 vh = make_uint4(0, 0, 0, 0);
            if (r < valid) vh = gh[r * 16 + c];
            *(uint4*)(smem + SM_AH + r * SAS + c * 16) = vh;
        }
    }
    {
        const uint4* wh = (const uint4*)(g_Whi + layer * DIM * DIM);
        const uint4* wl = (const uint4*)(g_Wlo + layer * DIM * DIM);
        #pragma unroll
        for (int i = tid; i < 2048; i += 128) {
            int r = i >> 4, c = i & 15;
            *(uint4*)(smem + SM_WH + r * SAS + c * 16) = wh[i];
            *(uint4*)(smem + SM_WL + r * SAS + c * 16) = wl[i];
        }
    }
    __syncthreads();

    float acc[16][4];
    #pragma unroll
    for (int j = 0; j < 16; j++)
        #pragma unroll
        for (int q = 0; q < 4; q++) acc[j][q] = 0.f;

    int wm = wid * 16;
    uint32_t a_off = (uint32_t)((wm + (lane & 15)) * SAS + ((lane >> 4) << 3) * 2);
    uint32_t b_off = (uint32_t)(((lane & 7) + ((lane >> 4) << 3)) * SAS + (((lane >> 3) & 1) << 3) * 2);

    for (int kk = 0; kk < 8; kk++) {
        uint32_t kb = kk * 32;
        uint32_t ah[4];
        ldsm4(sb + SM_AH + a_off + kb, ah);
        #pragma unroll
        for (int nt = 0; nt < 8; nt++) {
            uint32_t bh[4], bl[4];
            uint32_t nrow = nt * 16 * SAS;
            ldsm4(sb + SM_WH + nrow + b_off + kb, bh);
            ldsm4(sb + SM_WL + nrow + b_off + kb, bl);
            mma16816(acc[2 * nt],     ah, bh[0], bh[1]);
            mma16816(acc[2 * nt + 1], ah, bh[2], bh[3]);
            mma16816(acc[2 * nt],     ah, bl[0], bl[1]);
            mma16816(acc[2 * nt + 1], ah, bl[2], bl[3]);
        }
    }

    // ---- epilogue: per-row symmetric int8 quantization ----
    // thread holds rows r0 = m0+wm+(lane>>2) and r0+8; cols {j*8+cb, j*8+cb+1}, cb=(lane&3)*2.
    int r0 = m0 + wm + (lane >> 2);
    int cb = (lane & 3) * 2;

    float m0v = 0.f, m1v = 0.f;
    #pragma unroll
    for (int j = 0; j < 16; j++) {
        m0v = fmaxf(m0v, fmaxf(fabsf(acc[j][0]), fabsf(acc[j][1])));
        m1v = fmaxf(m1v, fmaxf(fabsf(acc[j][2]), fabsf(acc[j][3])));
    }
    // reduce across the quad of lanes sharing a row (xor 1, xor 2 stay within the quad)
    m0v = fmaxf(m0v, __shfl_xor_sync(0xffffffffu, m0v, 1));
    m0v = fmaxf(m0v, __shfl_xor_sync(0xffffffffu, m0v, 2));
    m1v = fmaxf(m1v, __shfl_xor_sync(0xffffffffu, m1v, 1));
    m1v = fmaxf(m1v, __shfl_xor_sync(0xffffffffu, m1v, 2));
    float i0 = (m0v > 0.f) ? 127.f / m0v : 0.f;
    float i1 = (m1v > 0.f) ? 127.f / m1v : 0.f;
    if ((lane & 3) == 0) {
        if (r0 < N_NODES)     g_rsc[r0]     = m0v * (1.f / 127.f);
        if (r0 + 8 < N_NODES) g_rsc[r0 + 8] = m1v * (1.f / 127.f);
    }
    if (r0 < N_NODES) {
        unsigned short* d = (unsigned short*)((char*)g_q + (long long)r0 * DIM) + (cb >> 1);
        #pragma unroll
        for (int j = 0; j < 16; j++) {
            int q0 = __float2int_rn(acc[j][0] * i0);
            int q1 = __float2int_rn(acc[j][1] * i0);
            d[j * 4] = (unsigned short)((q0 & 0xff) | ((q1 & 0xff) << 8));
        }
    }
    if (r0 + 8 < N_NODES) {
        unsigned short* d = (unsigned short*)((char*)g_q + (long long)(r0 + 8) * DIM) + (cb >> 1);
        #pragma unroll
        for (int j = 0; j < 16; j++) {
            int q0 = __float2int_rn(acc[j][2] * i1);
            int q1 = __float2int_rn(acc[j][3] * i1);
            d[j * 4] = (unsigned short)((q0 & 0xff) | ((q1 & 0xff) << 8));
        }
    }
}

// ---------------- SpMM: int8 gather (4B/lane), fp32 acc, relu, bf16 out ----
__device__ __forceinline__ void acc_edge_q(float4& acc, float c, int w) {
    acc.x += c * (float)((w << 24) >> 24);
    acc.y += c * (float)((w << 16) >> 24);
    acc.z += c * (float)((w << 8)  >> 24);
    acc.w += c * (float)( w        >> 24);
}

__global__ void __launch_bounds__(256) k_spmm(const float* __restrict__ bias) {
    int warp = (blockIdx.x * blockDim.x + threadIdx.x) >> 5;
    int lane = threadIdx.x & 31;
    if (warp >= N_NODES) return;
    int i = warp;

    float di = g_dinv[i];
    float4 acc = make_float4(0.f, 0.f, 0.f, 0.f);
    {
        float c = di * di * g_rsc[i];
        int w = g_q[i * 32 + lane];
        acc_edge_q(acc, c, w);
    }

    int p = g_off[i], pe = g_off[i + 1];
    for (; p + 4 <= pe; p += 4) {
        int   s0 = g_csrc[p],     s1 = g_csrc[p + 1];
        int   s2 = g_csrc[p + 2], s3 = g_csrc[p + 3];
        float c0 = g_cnrm[p]     * g_rsc[s0];
        float c1 = g_cnrm[p + 1] * g_rsc[s1];
        float c2 = g_cnrm[p + 2] * g_rsc[s2];
        float c3 = g_cnrm[p + 3] * g_rsc[s3];
        int w0 = g_q[s0 * 32 + lane];
        int w1 = g_q[s1 * 32 + lane];
        int w2 = g_q[s2 * 32 + lane];
        int w3 = g_q[s3 * 32 + lane];
        acc_edge_q(acc, c0, w0);
        acc_edge_q(acc, c1, w1);
        acc_edge_q(acc, c2, w2);
        acc_edge_q(acc, c3, w3);
    }
    for (; p < pe; p++) {
        int s = g_csrc[p];
        float c = g_cnrm[p] * g_rsc[s];
        int w = g_q[s * 32 + lane];
        acc_edge_q(acc, c, w);
    }

    float4 bv = ((const float4*)bias)[lane];
    acc.x = fmaxf(acc.x + bv.x, 0.f);
    acc.y = fmaxf(acc.y + bv.y, 0.f);
    acc.z = fmaxf(acc.z + bv.z, 0.f);
    acc.w = fmaxf(acc.w + bv.w, 0.f);

    // bf16 store for next layer's GEMM (and pool)
    uint2 ph;
    ph.x = packbf2(acc.x, acc.y);
    ph.y = packbf2(acc.z, acc.w);
    ((uint2*)g_Ahi)[(long long)i * 32 + lane] = ph;
}

// ---------------- global mean pool (batch is sorted; no atomics) ----------------
__device__ __forceinline__ int lbound(const void* __restrict__ b, int key) {
    int lo = 0, hi = N_NODES;
    while (lo < hi) {
        int mid = (lo + hi) >> 1;
        if (ldidx(b, mid) < key) lo = mid + 1; else hi = mid;
    }
    return lo;
}
__global__ void k_pool(const void* __restrict__ batch) {
    int g = blockIdx.x / PCH;
    int c = blockIdx.x % PCH;
    int t = threadIdx.x;
    int start = lbound(batch, g);
    int end   = lbound(batch, g + 1);
    int len = end - start;
    int rs = start + (int)((long long)len * c / PCH);
    int re = start + (int)((long long)len * (c + 1) / PCH);
    float s = 0.f;
    for (int r = rs; r < re; r++)
        s += __bfloat162float(g_Ahi[(long long)r * DIM + t]);
    g_pool[(c * NGRAPH + g) * DIM + t] = s;
}
__global__ void k_pool_div(const void* __restrict__ batch, float* __restrict__ out) {
    int g = blockIdx.x;
    int t = threadIdx.x;
    float s = 0.f;
    #pragma unroll
    for (int c = 0; c < PCH; c++) s += g_pool[(c * NGRAPH + g) * DIM + t];
    int start = lbound(batch, g);
    int end   = lbound(batch, g + 1);
    float cnt = (float)(end - start);
    if (cnt < 1.f) cnt = 1.f;
    out[g * DIM + t] = s / cnt;
}

// ---------------- launch ----------------
extern "C" void kernel_launch(void* const* d_in, const int* in_sizes, int n_in,
                              void* d_out, int out_size) {
    (void)out_size;
    const float* x = 0; const void* ei = 0; const void* batch = 0;
    const float* W[3] = {0, 0, 0}; const float* b[3] = {0, 0, 0};
    int nw = 0, nb = 0;
    for (int i = 0; i < n_in; i++) {
        int sz = in_sizes[i];
        if      (sz == N_NODES * DIM) x     = (const float*)d_in[i];
        else if (sz == 2 * N_EDGES)   ei    = d_in[i];
        else if (sz == N_NODES)       batch = d_in[i];
        else if (sz == DIM * DIM)     { if (nw < 3) W[nw++] = (const float*)d_in[i]; }
        else if (sz == DIM)           { if (nb < 3) b[nb++] = (const float*)d_in[i]; }
    }
    float* out = (float*)d_out;

    cudaFuncSetAttribute(k_gemm_mma, cudaFuncAttributeMaxDynamicSharedMemorySize, SM_TOT);

    const int NT = 256;
    int nblk = (N_NODES + NT - 1) / NT;
    int e2blk = (N_EDGES / 2 + NT - 1) / NT;
    int spmm_blocks = (N_NODES * 32 + NT - 1) / NT;
    int gemm_blocks = (N_NODES + 63) / 64;  // 782

    // preprocess (4 launches)
    k_init<<<nblk, NT>>>((const int*)ei);
    k_degree<<<e2blk, NT>>>(ei);
    k_scan<<<1, 1024>>>();
    k_fill<<<e2blk, NT>>>(ei, W[0], W[1], W[2]);

    // layers (6 launches); layer 0 stages bf16(x) directly
    k_gemm_mma<<<gemm_blocks, 128, SM_TOT>>>(0, x);
    k_spmm<<<spmm_blocks, NT>>>(b[0]);
    k_gemm_mma<<<gemm_blocks, 128, SM_TOT>>>(1, nullptr);
    k_spmm<<<spmm_blocks, NT>>>(b[1]);
    k_gemm_mma<<<gemm_blocks, 128, SM_TOT>>>(2, nullptr);
    k_spmm<<<spmm_blocks, NT>>>(b[2]);

    // pool (2 launches, no atomics)
    k_pool<<<NGRAPH * PCH, DIM>>>(batch);
    k_pool_div<<<NGRAPH, DIM>>>(batch, out);
}

// round 12
// speedup vs baseline: 1.1349x; 1.1349x over previous
#include <cuda_runtime.h>
#include <cuda_bf16.h>
#include <cuda_fp16.h>
#include <cstdint>

#define N_NODES 50000
#define N_EDGES 800000
#define DIM     128
#define NGRAPH  64

// ---------------- scratch (static device globals; no allocation) ----------------
__device__ __nv_bfloat16 g_Ahi[N_NODES * DIM];   // GEMM input (bf16)
__device__ __half        g_hw [N_NODES * DIM];   // GEMM output (SpMM gather input, fp16)
__device__ __nv_bfloat16 g_Whi[3 * DIM * DIM];   // W^T hi  [layer][n][k]
__device__ __nv_bfloat16 g_Wlo[3 * DIM * DIM];   // W^T lo  [layer][n][k]  (W error is node-correlated
                                                 //  -> does NOT pool-average; split required)
__device__ int   g_deg[N_NODES];
__device__ float g_dinv[N_NODES];
__device__ int   g_off[N_NODES + 1];
__device__ int   g_cur[N_NODES];                 // preloaded with offsets by k_scan
__device__ int2  g_edge[N_EDGES];                // {src, norm as float bits} fused -> 1 line/edge
__device__ int   g_is64;
#define PCH 16
__device__ float g_pool[PCH * NGRAPH * DIM];

// ---------------- small helpers ----------------
__device__ __forceinline__ int ldidx(const void* __restrict__ p, long long i) {
    if (g_is64) return (int)((const long long*)p)[i];
    return ((const int*)p)[i];
}
__device__ __forceinline__ uint32_t smem_u32(const void* p) {
    uint32_t a;
    asm("{ .reg .u64 t; cvta.to.shared.u64 t, %1; cvt.u32.u64 %0, t; }" : "=r"(a) : "l"(p));
    return a;
}
__device__ __forceinline__ uint32_t packbf2(float a, float b) {
    __nv_bfloat162 t = __floats2bfloat162_rn(a, b);
    return *reinterpret_cast<uint32_t*>(&t);
}
__device__ __forceinline__ float2 h2f2(uint32_t u) {
    __half2 h = *reinterpret_cast<__half2*>(&u);
    return __half22float2(h);
}

// ---------------- init + dtype detection (fused) ----------------
__global__ void k_init(const int* __restrict__ probe) {
    int i = blockIdx.x * blockDim.x + threadIdx.x;
    if (i < N_NODES) g_deg[i] = 0;
    if (blockIdx.x == 0) {
        __shared__ int nz;
        if (threadIdx.x == 0) nz = 0;
        __syncthreads();
        if (threadIdx.x < 256 && probe[threadIdx.x * 2 + 1] != 0) atomicAdd(&nz, 1);
        __syncthreads();
        if (threadIdx.x == 0) g_is64 = (nz == 0) ? 1 : 0;
    }
}

// 2 edges per thread, vectorized dst loads
__global__ void k_degree(const void* __restrict__ ei) {
    int t = blockIdx.x * blockDim.x + threadIdx.x;
    if (t >= N_EDGES / 2) return;
    int d0, d1;
    if (g_is64) {
        longlong2 v = ((const longlong2*)((const long long*)ei + N_EDGES))[t];
        d0 = (int)v.x; d1 = (int)v.y;
    } else {
        int2 v = ((const int2*)((const int*)ei + N_EDGES))[t];
        d0 = v.x; d1 = v.y;
    }
    atomicAdd(&g_deg[d0], 1);
    atomicAdd(&g_deg[d1], 1);
}

// scan; dinv fused; preloads g_cur with the running offset (fill uses 1 atomic)
__global__ void k_scan() {
    __shared__ int part[1024];
    const int CH = (N_NODES + 1023) / 1024;
    int t = threadIdx.x;
    int b = t * CH;
    int e = b + CH; if (e > N_NODES) e = N_NODES;
    int s = 0;
    for (int i = b; i < e; i++) {
        int d = g_deg[i];
        g_dinv[i] = rsqrtf((float)(d + 1));
        s += d;
    }
    part[t] = s;
    __syncthreads();
    for (int d = 1; d < 1024; d <<= 1) {
        int v = (t >= d) ? part[t - d] : 0;
        __syncthreads();
        part[t] += v;
        __syncthreads();
    }
    int run = (t > 0) ? part[t - 1] : 0;
    for (int i = b; i < e; i++) {
        g_off[i] = run;
        g_cur[i] = run;
        run += g_deg[i];
    }
    if (t == 1023) g_off[N_NODES] = part[1023];
}

// fill CSR (2 edges/thread, 1 atomic + 1 fused 8B store per edge);
// low threads also transpose/split W (fused prepW)
__global__ void k_fill(const void* __restrict__ ei, const float* __restrict__ W0,
                       const float* __restrict__ W1, const float* __restrict__ W2) {
    int t = blockIdx.x * blockDim.x + threadIdx.x;
    if (t < 3 * DIM * DIM) {
        int L = t >> 14;
        int idx = t & (DIM * DIM - 1);
        const float* W = (L == 0) ? W0 : (L == 1) ? W1 : W2;
        int k = idx >> 7, n = idx & 127;
        float v = W[idx];
        __nv_bfloat16 hi = __float2bfloat16_rn(v);
        float lo = v - __bfloat162float(hi);
        g_Whi[L * DIM * DIM + n * DIM + k] = hi;
        g_Wlo[L * DIM * DIM + n * DIM + k] = __float2bfloat16_rn(lo);
    }
    if (t >= N_EDGES / 2) return;
    int s0, s1, d0, d1;
    if (g_is64) {
        longlong2 sv = ((const longlong2*)ei)[t];
        longlong2 dv = ((const longlong2*)((const long long*)ei + N_EDGES))[t];
        s0 = (int)sv.x; s1 = (int)sv.y; d0 = (int)dv.x; d1 = (int)dv.y;
    } else {
        int2 sv = ((const int2*)ei)[t];
        int2 dv = ((const int2*)((const int*)ei + N_EDGES))[t];
        s0 = sv.x; s1 = sv.y; d0 = dv.x; d1 = dv.y;
    }
    float n0 = g_dinv[s0] * g_dinv[d0];
    float n1 = g_dinv[s1] * g_dinv[d1];
    int p0 = atomicAdd(&g_cur[d0], 1);
    int p1 = atomicAdd(&g_cur[d1], 1);
    g_edge[p0] = make_int2(s0, __float_as_int(n0));
    g_edge[p1] = make_int2(s1, __float_as_int(n1));
}

// ---------------- mma.sync GEMM: g_hw[m][n] = sum_k A[m][k] * W[k][n] ----------------
// A bf16, W bf16 split (2 products), fp32 accum, fp16 out.
// Block: 128 threads (4 warps), tile M=64, N=128, K=128. Layer 0 stages bf16(x).
#define SAS 272                 // smem row stride in BYTES (136 bf16)
#define SM_AH 0
#define SM_WH (64 * SAS)
#define SM_WL (192 * SAS)
#define SM_TOT (320 * SAS)      // 87,040 B

__device__ __forceinline__ void ldsm4(uint32_t addr, uint32_t* r) {
    asm volatile("ldmatrix.sync.aligned.m8n8.x4.shared.b16 {%0,%1,%2,%3}, [%4];"
                 : "=r"(r[0]), "=r"(r[1]), "=r"(r[2]), "=r"(r[3]) : "r"(addr));
}
__device__ __forceinline__ void mma16816(float* d, const uint32_t* a, uint32_t b0, uint32_t b1) {
    asm volatile(
        "mma.sync.aligned.m16n8k16.row.col.f32.bf16.bf16.f32 "
        "{%0,%1,%2,%3}, {%4,%5,%6,%7}, {%8,%9}, {%0,%1,%2,%3};"
        : "+f"(d[0]), "+f"(d[1]), "+f"(d[2]), "+f"(d[3])
        : "r"(a[0]), "r"(a[1]), "r"(a[2]), "r"(a[3]), "r"(b0), "r"(b1));
}

__global__ void __launch_bounds__(128) k_gemm_mma(int layer, const float* __restrict__ xsrc) {
    extern __shared__ char smem[];
    uint32_t sb = smem_u32(smem);
    int tid = threadIdx.x, wid = tid >> 5, lane = tid & 31;
    int m0 = blockIdx.x * 64;
    int valid = N_NODES - m0; if (valid > 64) valid = 64;

    // stage A (64 x 128 bf16)
    if (xsrc) {
        #pragma unroll
        for (int i = tid; i < 1024; i += 128) {
            int r = i >> 4, c = i & 15;
            uint4 vh = make_uint4(0, 0, 0, 0);
            if (r < valid) {
                const float4* xr = (const float4*)(xsrc + (long long)(m0 + r) * DIM) + c * 2;
                float4 f0 = xr[0], f1 = xr[1];
                vh.x = packbf2(f0.x, f0.y);
                vh.y = packbf2(f0.z, f0.w);
                vh.z = packbf2(f1.x, f1.y);
                vh.w = packbf2(f1.z, f1.w);
            }
            *(uint4*)(smem + SM_AH + r * SAS + c * 16) = vh;
        }
    } else {
        const uint4* gh = (const uint4*)(g_Ahi + (long long)m0 * DIM);
        #pragma unroll
        for (int i = tid; i < 1024; i += 128) {
            int r = i >> 4, c = i & 15;
            uint4 vh = make_uint4(0, 0, 0, 0);
            if (r < valid) vh = gh[r * 16 + c];
            *(uint4*)(smem + SM_AH + r * SAS + c * 16) = vh;
        }
    }
    {
        const uint4* wh = (const uint4*)(g_Whi + layer * DIM * DIM);
        const uint4* wl = (const uint4*)(g_Wlo + layer * DIM * DIM);
        #pragma unroll
        for (int i = tid; i < 2048; i += 128) {
            int r = i >> 4, c = i & 15;
            *(uint4*)(smem + SM_WH + r * SAS + c * 16) = wh[i];
            *(uint4*)(smem + SM_WL + r * SAS + c * 16) = wl[i];
        }
    }
    __syncthreads();

    float acc[16][4];
    #pragma unroll
    for (int j = 0; j < 16; j++)
        #pragma unroll
        for (int q = 0; q < 4; q++) acc[j][q] = 0.f;

    int wm = wid * 16;
    uint32_t a_off = (uint32_t)((wm + (lane & 15)) * SAS + ((lane >> 4) << 3) * 2);
    uint32_t b_off = (uint32_t)(((lane & 7) + ((lane >> 4) << 3)) * SAS + (((lane >> 3) & 1) << 3) * 2);

    for (int kk = 0; kk < 8; kk++) {
        uint32_t kb = kk * 32;
        uint32_t ah[4];
        ldsm4(sb + SM_AH + a_off + kb, ah);
        #pragma unroll
        for (int nt = 0; nt < 8; nt++) {
            uint32_t bh[4], bl[4];
            uint32_t nrow = nt * 16 * SAS;
            ldsm4(sb + SM_WH + nrow + b_off + kb, bh);
            ldsm4(sb + SM_WL + nrow + b_off + kb, bl);
            mma16816(acc[2 * nt],     ah, bh[0], bh[1]);
            mma16816(acc[2 * nt + 1], ah, bh[2], bh[3]);
            mma16816(acc[2 * nt],     ah, bl[0], bl[1]);
            mma16816(acc[2 * nt + 1], ah, bl[2], bl[3]);
        }
    }

    // epilogue: fp16 output
    int r0 = m0 + wm + (lane >> 2);
    int cb = (lane & 3) * 2;
    if (r0 < N_NODES) {
        __half* d = g_hw + (long long)r0 * DIM;
        #pragma unroll
        for (int j = 0; j < 16; j++)
            *(__half2*)(d + j * 8 + cb) = __floats2half2_rn(acc[j][0], acc[j][1]);
    }
    if (r0 + 8 < N_NODES) {
        __half* d = g_hw + (long long)(r0 + 8) * DIM;
        #pragma unroll
        for (int j = 0; j < 16; j++)
            *(__half2*)(d + j * 8 + cb) = __floats2half2_rn(acc[j][2], acc[j][3]);
    }
}

// ---------------- SpMM: fp16 gather (4-wide), fused edge loads, fp32 acc, relu, bf16 out ----
__device__ __forceinline__ void acc_edge(float4& acc, float n, uint2 v) {
    float2 a = h2f2(v.x), b = h2f2(v.y);
    acc.x += n * a.x; acc.y += n * a.y; acc.z += n * b.x; acc.w += n * b.y;
}

__global__ void __launch_bounds__(256) k_spmm(const float* __restrict__ bias) {
    int warp = (blockIdx.x * blockDim.x + threadIdx.x) >> 5;
    int lane = threadIdx.x & 31;
    if (warp >= N_NODES) return;
    int i = warp;

    float di = g_dinv[i];
    float sl = di * di;
    float4 acc;
    {
        uint2 v = ((const uint2*)(g_hw + (long long)i * DIM))[lane];
        float2 a = h2f2(v.x), b = h2f2(v.y);
        acc = make_float4(sl * a.x, sl * a.y, sl * b.x, sl * b.y);
    }

    int p = g_off[i], pe = g_off[i + 1];
    for (; p + 4 <= pe; p += 4) {
        int2 e0 = g_edge[p],     e1 = g_edge[p + 1];
        int2 e2 = g_edge[p + 2], e3 = g_edge[p + 3];
        uint2 v0 = ((const uint2*)(g_hw + (long long)e0.x * DIM))[lane];
        uint2 v1 = ((const uint2*)(g_hw + (long long)e1.x * DIM))[lane];
        uint2 v2 = ((const uint2*)(g_hw + (long long)e2.x * DIM))[lane];
        uint2 v3 = ((const uint2*)(g_hw + (long long)e3.x * DIM))[lane];
        acc_edge(acc, __int_as_float(e0.y), v0);
        acc_edge(acc, __int_as_float(e1.y), v1);
        acc_edge(acc, __int_as_float(e2.y), v2);
        acc_edge(acc, __int_as_float(e3.y), v3);
    }
    for (; p < pe; p++) {
        int2 e = g_edge[p];
        uint2 v = ((const uint2*)(g_hw + (long long)e.x * DIM))[lane];
        acc_edge(acc, __int_as_float(e.y), v);
    }

    float4 bv = ((const float4*)bias)[lane];
    acc.x = fmaxf(acc.x + bv.x, 0.f);
    acc.y = fmaxf(acc.y + bv.y, 0.f);
    acc.z = fmaxf(acc.z + bv.z, 0.f);
    acc.w = fmaxf(acc.w + bv.w, 0.f);

    // bf16 store for next layer's GEMM (and pool)
    uint2 ph;
    ph.x = packbf2(acc.x, acc.y);
    ph.y = packbf2(acc.z, acc.w);
    ((uint2*)g_Ahi)[(long long)i * 32 + lane] = ph;
}

// ---------------- global mean pool (batch is sorted; no atomics) ----------------
__device__ __forceinline__ int lbound(const void* __restrict__ b, int key) {
    int lo = 0, hi = N_NODES;
    while (lo < hi) {
        int mid = (lo + hi) >> 1;
        if (ldidx(b, mid) < key) lo = mid + 1; else hi = mid;
    }
    return lo;
}
__global__ void k_pool(const void* __restrict__ batch) {
    int g = blockIdx.x / PCH;
    int c = blockIdx.x % PCH;
    int t = threadIdx.x;
    int start = lbound(batch, g);
    int end   = lbound(batch, g + 1);
    int len = end - start;
    int rs = start + (int)((long long)len * c / PCH);
    int re = start + (int)((long long)len * (c + 1) / PCH);
    float s = 0.f;
    for (int r = rs; r < re; r++)
        s += __bfloat162float(g_Ahi[(long long)r * DIM + t]);
    g_pool[(c * NGRAPH + g) * DIM + t] = s;
}
__global__ void k_pool_div(const void* __restrict__ batch, float* __restrict__ out) {
    int g = blockIdx.x;
    int t = threadIdx.x;
    float s = 0.f;
    #pragma unroll
    for (int c = 0; c < PCH; c++) s += g_pool[(c * NGRAPH + g) * DIM + t];
    int start = lbound(batch, g);
    int end   = lbound(batch, g + 1);
    float cnt = (float)(end - start);
    if (cnt < 1.f) cnt = 1.f;
    out[g * DIM + t] = s / cnt;
}

// ---------------- launch ----------------
extern "C" void kernel_launch(void* const* d_in, const int* in_sizes, int n_in,
                              void* d_out, int out_size) {
    (void)out_size;
    const float* x = 0; const void* ei = 0; const void* batch = 0;
    const float* W[3] = {0, 0, 0}; const float* b[3] = {0, 0, 0};
    int nw = 0, nb = 0;
    for (int i = 0; i < n_in; i++) {
        int sz = in_sizes[i];
        if      (sz == N_NODES * DIM) x     = (const float*)d_in[i];
        else if (sz == 2 * N_EDGES)   ei    = d_in[i];
        else if (sz == N_NODES)       batch = d_in[i];
        else if (sz == DIM * DIM)     { if (nw < 3) W[nw++] = (const float*)d_in[i]; }
        else if (sz == DIM)           { if (nb < 3) b[nb++] = (const float*)d_in[i]; }
    }
    float* out = (float*)d_out;

    cudaFuncSetAttribute(k_gemm_mma, cudaFuncAttributeMaxDynamicSharedMemorySize, SM_TOT);

    const int NT = 256;
    int nblk = (N_NODES + NT - 1) / NT;
    int e2blk = (N_EDGES / 2 + NT - 1) / NT;
    int spmm_blocks = (N_NODES * 32 + NT - 1) / NT;
    int gemm_blocks = (N_NODES + 63) / 64;  // 782

    // preprocess (4 launches)
    k_init<<<nblk, NT>>>((const int*)ei);
    k_degree<<<e2blk, NT>>>(ei);
    k_scan<<<1, 1024>>>();
    k_fill<<<e2blk, NT>>>(ei, W[0], W[1], W[2]);

    // layers (6 launches); layer 0 stages bf16(x) directly
    k_gemm_mma<<<gemm_blocks, 128, SM_TOT>>>(0, x);
    k_spmm<<<spmm_blocks, NT>>>(b[0]);
    k_gemm_mma<<<gemm_blocks, 128, SM_TOT>>>(1, nullptr);
    k_spmm<<<spmm_blocks, NT>>>(b[1]);
    k_gemm_mma<<<gemm_blocks, 128, SM_TOT>>>(2, nullptr);
    k_spmm<<<spmm_blocks, NT>>>(b[2]);

    // pool (2 launches, no atomics)
    k_pool<<<NGRAPH * PCH, DIM>>>(batch);
    k_pool_div<<<NGRAPH, DIM>>>(batch, out);
}